// round 16
// baseline (speedup 1.0000x reference)
#include <cuda_runtime.h>

#define NN 50000
#define EE 800000
#define GG 500
#define CH 128
#define EF 16
#define NL 4
#define NC 10
#define BN_EPS 1e-5f

// packed-f32x2 FMA (Blackwell): d.{lo,hi} += a.{lo,hi} * b.{lo,hi}
#define FMA2(d, a, b) asm("fma.rn.f32x2 %0, %1, %2, %0;" : "+l"(d) : "l"(a), "l"(b))

#define TR 8                // rows per warp (GEMM)
#define NWARP 8             // warps per block (GEMM)
#define TILE (NWARP * TR)   // 64 rows per block

// ------------------------- scratch (device globals, no allocation) ---------
__device__ __align__(16) float g_h[NN * CH];
__device__ __align__(16) float g_x[NN * CH];
__device__ __align__(16) float g_z[NN * CH];
__device__ __align__(16) float g_ea[NN * EF];
__device__ int   g_deg[NN];
__device__ int   g_rowptr[NN + 1];
__device__ int   g_cursor[NN];
__device__ int   g_col[EE];   // CSR: src sorted by dst
__device__ int   g_eid[EE];   // CSR: edge id sorted by dst
__device__ int   g_bsum[64];
__device__ __align__(16) float g_stats[NL * 2 * CH];
__device__ __align__(16) float g_pooled[(NL + 1) * GG * CH];

// ------------------------- degree count ------------------------------------
__global__ void k_deg(const int* __restrict__ ei) {
    int e = blockIdx.x * blockDim.x + threadIdx.x;
    if (e >= EE) return;
    atomicAdd(&g_deg[ei[EE + e]], 1);
}

// ------------------------- scan pass 1: per-block sums ---------------------
__global__ void k_scan1() {
    __shared__ int s[1024];
    int i = blockIdx.x * 1024 + threadIdx.x;
    s[threadIdx.x] = (i < NN) ? g_deg[i] : 0;
    __syncthreads();
    for (int off = 512; off > 0; off >>= 1) {
        if (threadIdx.x < off) s[threadIdx.x] += s[threadIdx.x + off];
        __syncthreads();
    }
    if (threadIdx.x == 0) g_bsum[blockIdx.x] = s[0];
}

// ------------- scan pass 2: per-block base + local scan --------------------
__global__ void k_scan3(int nb) {
    __shared__ int s[1024];
    __shared__ int base;
    if (threadIdx.x == 0) {
        int run = 0;
        for (int b = 0; b < blockIdx.x; b++) run += g_bsum[b];
        base = run;
        if (blockIdx.x == 0) g_rowptr[NN] = EE;
    }
    int i = blockIdx.x * 1024 + threadIdx.x;
    int v = (i < NN) ? g_deg[i] : 0;
    s[threadIdx.x] = v;
    __syncthreads();
    for (int off = 1; off < 1024; off <<= 1) {
        int t = (threadIdx.x >= off) ? s[threadIdx.x - off] : 0;
        __syncthreads();
        s[threadIdx.x] += t;
        __syncthreads();
    }
    if (i < NN) {
        int r = s[threadIdx.x] - v + base;
        g_rowptr[i] = r;
        g_cursor[i] = r;
    }
}

// ------------------------- CSR fill ----------------------------------------
__global__ void k_fill(const int* __restrict__ ei) {
    int e = blockIdx.x * blockDim.x + threadIdx.x;
    if (e >= EE) return;
    int d = ei[EE + e];
    int pos = atomicAdd(&g_cursor[d], 1);
    g_col[pos] = ei[e];
    g_eid[pos] = e;
}

// ------------------------- ea = segment_sum(edge_attr, dst) ----------------
__global__ void k_ea(const float* __restrict__ eattr) {
    int idx = blockIdx.x * blockDim.x + threadIdx.x;
    int n = idx >> 4;
    if (n >= NN) return;
    int k = idx & 15;
    int beg = g_rowptr[n], end = g_rowptr[n + 1];
    float a0 = 0.f, a1 = 0.f;
    int e = beg;
    for (; e + 2 <= end; e += 2) {
        int i0 = g_eid[e], i1 = g_eid[e + 1];
        a0 += eattr[(size_t)i0 * EF + k];
        a1 += eattr[(size_t)i1 * EF + k];
    }
    if (e < end) a0 += eattr[(size_t)g_eid[e] * EF + k];
    g_ea[(size_t)n * EF + k] = a0 + a1;
}

// ---------- aggregate (standalone, high occupancy): x = h + deg*be + ea@We
// ---------- + sum h[src] ; warp per node, MLP=8 on the edge loop -----------
__global__ void __launch_bounds__(256)
k_aggregate(const float* __restrict__ We, const float* __restrict__ be) {
    __shared__ float Wes[EF * CH];
    __shared__ float bes[CH];
    for (int i = threadIdx.x; i < EF * CH; i += blockDim.x) Wes[i] = We[i];
    if (threadIdx.x < CH) bes[threadIdx.x] = be[threadIdx.x];
    __syncthreads();

    int n = (blockIdx.x * blockDim.x + threadIdx.x) >> 5;
    if (n >= NN) return;
    int lane = threadIdx.x & 31;
    int c0 = lane * 4;

    float4 acc = *(const float4*)(g_h + (size_t)n * CH + c0);
    float4 ac2 = make_float4(0.f, 0.f, 0.f, 0.f);
    float4 ac3 = make_float4(0.f, 0.f, 0.f, 0.f);
    float4 ac4 = make_float4(0.f, 0.f, 0.f, 0.f);

    int beg = g_rowptr[n], end = g_rowptr[n + 1];
    float dg = (float)(end - beg);
    float4 b4 = *(const float4*)&bes[c0];
    acc.x += dg * b4.x; acc.y += dg * b4.y;
    acc.z += dg * b4.z; acc.w += dg * b4.w;

#pragma unroll
    for (int k = 0; k < EF; k++) {
        float ev = g_ea[(size_t)n * EF + k];
        float4 w = *(const float4*)&Wes[k * CH + c0];
        acc.x += ev * w.x; acc.y += ev * w.y;
        acc.z += ev * w.z; acc.w += ev * w.w;
    }

    int e = beg;
    for (; e + 8 <= end; e += 8) {
        int s0 = g_col[e],     s1 = g_col[e + 1];
        int s2 = g_col[e + 2], s3 = g_col[e + 3];
        int s4 = g_col[e + 4], s5 = g_col[e + 5];
        int s6 = g_col[e + 6], s7 = g_col[e + 7];
        float4 v0 = *(const float4*)(g_h + (size_t)s0 * CH + c0);
        float4 v1 = *(const float4*)(g_h + (size_t)s1 * CH + c0);
        float4 v2 = *(const float4*)(g_h + (size_t)s2 * CH + c0);
        float4 v3 = *(const float4*)(g_h + (size_t)s3 * CH + c0);
        float4 v4 = *(const float4*)(g_h + (size_t)s4 * CH + c0);
        float4 v5 = *(const float4*)(g_h + (size_t)s5 * CH + c0);
        float4 v6 = *(const float4*)(g_h + (size_t)s6 * CH + c0);
        float4 v7 = *(const float4*)(g_h + (size_t)s7 * CH + c0);
        acc.x += v0.x + v1.x; ac2.x += v2.x + v3.x;
        ac3.x += v4.x + v5.x; ac4.x += v6.x + v7.x;
        acc.y += v0.y + v1.y; ac2.y += v2.y + v3.y;
        ac3.y += v4.y + v5.y; ac4.y += v6.y + v7.y;
        acc.z += v0.z + v1.z; ac2.z += v2.z + v3.z;
        ac3.z += v4.z + v5.z; ac4.z += v6.z + v7.z;
        acc.w += v0.w + v1.w; ac2.w += v2.w + v3.w;
        ac3.w += v4.w + v5.w; ac4.w += v6.w + v7.w;
    }
    for (; e + 2 <= end; e += 2) {
        int s0 = g_col[e], s1 = g_col[e + 1];
        float4 v0 = *(const float4*)(g_h + (size_t)s0 * CH + c0);
        float4 v1 = *(const float4*)(g_h + (size_t)s1 * CH + c0);
        ac2.x += v0.x + v1.x; ac2.y += v0.y + v1.y;
        ac2.z += v0.z + v1.z; ac2.w += v0.w + v1.w;
    }
    if (e < end) {
        int s = g_col[e];
        float4 v = *(const float4*)(g_h + (size_t)s * CH + c0);
        ac3.x += v.x; ac3.y += v.y; ac3.z += v.z; ac3.w += v.w;
    }
    acc.x += (ac2.x + ac3.x) + ac4.x;
    acc.y += (ac2.y + ac3.y) + ac4.y;
    acc.z += (ac2.z + ac3.z) + ac4.z;
    acc.w += (ac2.w + ac3.w) + ac4.w;

    *(float4*)(g_x + (size_t)n * CH + c0) = acc;
}

// ============ GEMM core: rotated-transposed W, pack-free f32x2 =============
// Wt[c][k] stored at c*128 + ((k + 4*(c&7)) & 127): conflict-free LDS.128
// (quad-bank = (k/4 + c) mod 8, distinct per 8-lane phase). Lane owns cols
// {lane, lane+32, lane+64, lane+96}; acc[r][j] is f32x2 over (even,odd) k.
// x reads are warp-broadcast LDS.128. Zero packing instructions.
template <bool STATS>
__device__ __forceinline__ void gemm_tile_t(
    const float* __restrict__ Wt, const float* __restrict__ xs,
    const float* __restrict__ bs,
    int tile, int r0, int lane, float* __restrict__ Z,
    float* cs, float* cq) {

    unsigned long long acc[TR][4];
#pragma unroll
    for (int r = 0; r < TR; r++)
#pragma unroll
        for (int j = 0; j < 4; j++) acc[r][j] = 0ull;

    const int lrot = 4 * (lane & 7);

#pragma unroll 2
    for (int k = 0; k < CH; k += 4) {
        int rotk = (k + lrot) & 127;
        ulonglong2 w0 = *(const ulonglong2*)&Wt[(lane +  0) * CH + rotk];
        ulonglong2 w1 = *(const ulonglong2*)&Wt[(lane + 32) * CH + rotk];
        ulonglong2 w2 = *(const ulonglong2*)&Wt[(lane + 64) * CH + rotk];
        ulonglong2 w3 = *(const ulonglong2*)&Wt[(lane + 96) * CH + rotk];
#pragma unroll
        for (int r = 0; r < TR; r++) {
            ulonglong2 xp = *(const ulonglong2*)&xs[(r0 + r) * CH + k];  // broadcast
            FMA2(acc[r][0], xp.x, w0.x);
            FMA2(acc[r][1], xp.x, w1.x);
            FMA2(acc[r][2], xp.x, w2.x);
            FMA2(acc[r][3], xp.x, w3.x);
            FMA2(acc[r][0], xp.y, w0.y);
            FMA2(acc[r][1], xp.y, w1.y);
            FMA2(acc[r][2], xp.y, w2.y);
            FMA2(acc[r][3], xp.y, w3.y);
        }
    }

#pragma unroll
    for (int r = 0; r < TR; r++) {
        int m = tile + r0 + r;
        if (m < NN) {
#pragma unroll
            for (int j = 0; j < 4; j++) {
                int c = lane + 32 * j;
                float lo = __uint_as_float((unsigned)acc[r][j]);
                float hi = __uint_as_float((unsigned)(acc[r][j] >> 32));
                float v = lo + hi + bs[c];
                Z[(size_t)m * CH + c] = v;
                if (STATS) { cs[j] += v; cq[j] += v * v; }
            }
        }
    }
}

// ------------------------- GEMM: Z = X@W + b (+ optional BN stats) ----------
template <bool STATS>
__global__ void __launch_bounds__(256, 2)
k_gemm(const float* __restrict__ X, const float* __restrict__ W,
       const float* __restrict__ B, float* __restrict__ Z,
       float* __restrict__ stats) {
    extern __shared__ float sm[];
    float* Wt = sm;                  // 128*128 (rotated transposed)
    float* bs = Wt + CH * CH;        // 128
    float* xs = bs + CH;             // TILE*128

    for (int i = threadIdx.x; i < CH * CH; i += 256) {
        int k = i >> 7, c = i & 127;
        Wt[c * CH + ((k + 4 * (c & 7)) & 127)] = W[i];
    }
    if (threadIdx.x < CH) bs[threadIdx.x] = B[threadIdx.x];
    __syncthreads();

    int warp = threadIdx.x >> 5, lane = threadIdx.x & 31;
    int c0 = lane * 4, r0 = warp * TR;
    float cs[4] = {0.f, 0.f, 0.f, 0.f};
    float cq[4] = {0.f, 0.f, 0.f, 0.f};

    for (int tile = blockIdx.x * TILE; tile < NN; tile += gridDim.x * TILE) {
#pragma unroll
        for (int r = 0; r < TR; r++) {
            int m = tile + r0 + r;
            float4 v = make_float4(0.f, 0.f, 0.f, 0.f);
            if (m < NN) v = *(const float4*)(X + (size_t)m * CH + c0);
            *(float4*)&xs[(r0 + r) * CH + c0] = v;
        }
        __syncwarp();   // warp-private slice: intra-warp ordering only
        gemm_tile_t<STATS>(Wt, xs, bs, tile, r0, lane, Z, cs, cq);
        __syncwarp();   // WAR before next overwrite
    }

    if (STATS) {
        __syncthreads();
        float* sr = xs;
        sr[threadIdx.x] = 0.f;
        __syncthreads();
#pragma unroll
        for (int j = 0; j < 4; j++) {
            int c = lane + 32 * j;
            atomicAdd(&sr[c], cs[j]);
            atomicAdd(&sr[CH + c], cq[j]);
        }
        __syncthreads();
        atomicAdd(&stats[threadIdx.x], sr[threadIdx.x]);
    }
}

// --- BN(from stats) + relu + residual + partial pool: grid (GG, 4) ---------
__global__ void k_poolbn(const float* __restrict__ stats,
                         const float* __restrict__ gamma,
                         const float* __restrict__ beta,
                         const int* __restrict__ batch,
                         float* __restrict__ pooled) {
    __shared__ int s_lo, s_hi;
    int g = blockIdx.x, part = blockIdx.y, c = threadIdx.x;

    float mu = stats[c] * (1.0f / NN);
    float var = stats[CH + c] * (1.0f / NN) - mu * mu;
    float sc = gamma[c] * rsqrtf(var + BN_EPS);
    float sh = beta[c] - mu * sc;

    if (c < 2) {
        int tgt = g + c;
        int lo = 0, hi = NN;
        while (lo < hi) {
            int mid = (lo + hi) >> 1;
            if (batch[mid] < tgt) lo = mid + 1; else hi = mid;
        }
        if (c == 0) s_lo = lo; else s_hi = lo;
    }
    __syncthreads();
    int gs = s_lo, ge = s_hi;
    int len = ge - gs;
    int per = (len + 3) >> 2;
    int lo = gs + part * per;
    int hi = lo + per; if (hi > ge) hi = ge;
    if (lo >= hi) { return; }

    float a0 = 0.f, a1 = 0.f;
    int n = lo;
    for (; n + 2 <= hi; n += 2) {
        float z0 = g_z[(size_t)n * CH + c];
        float h0 = g_h[(size_t)n * CH + c];
        float z1 = g_z[(size_t)(n + 1) * CH + c];
        float h1 = g_h[(size_t)(n + 1) * CH + c];
        float o0 = fmaxf(fmaf(z0, sc, sh), 0.f) + h0;
        float o1 = fmaxf(fmaf(z1, sc, sh), 0.f) + h1;
        g_h[(size_t)n * CH + c] = o0;
        g_h[(size_t)(n + 1) * CH + c] = o1;
        a0 += o0; a1 += o1;
    }
    if (n < hi) {
        float z0 = g_z[(size_t)n * CH + c];
        float h0 = g_h[(size_t)n * CH + c];
        float o0 = fmaxf(fmaf(z0, sc, sh), 0.f) + h0;
        g_h[(size_t)n * CH + c] = o0;
        a0 += o0;
    }
    atomicAdd(&pooled[(size_t)g * CH + c], a0 + a1);
}

// ------------------------- pool layer 0: grid (GG, 4) ----------------------
__global__ void k_pool0(const int* __restrict__ batch, float* __restrict__ pooled) {
    __shared__ int s_lo, s_hi;
    int g = blockIdx.x, part = blockIdx.y, c = threadIdx.x;
    if (c < 2) {
        int tgt = g + c;
        int lo = 0, hi = NN;
        while (lo < hi) {
            int mid = (lo + hi) >> 1;
            if (batch[mid] < tgt) lo = mid + 1; else hi = mid;
        }
        if (c == 0) s_lo = lo; else s_hi = lo;
    }
    __syncthreads();
    int gs = s_lo, ge = s_hi;
    int len = ge - gs;
    int per = (len + 3) >> 2;
    int lo = gs + part * per;
    int hi = lo + per; if (hi > ge) hi = ge;
    if (lo >= hi) return;

    float a0 = 0.f, a1 = 0.f;
    int n = lo;
    for (; n + 2 <= hi; n += 2) {
        a0 += g_h[(size_t)n * CH + c];
        a1 += g_h[(size_t)(n + 1) * CH + c];
    }
    if (n < hi) a0 += g_h[(size_t)n * CH + c];
    atomicAdd(&pooled[(size_t)g * CH + c], a0 + a1);
}

// ------------------------- JK heads ----------------------------------------
__global__ void k_jk(const float* __restrict__ jkW, const float* __restrict__ jkb,
                     float* __restrict__ out) {
    int idx = blockIdx.x * blockDim.x + threadIdx.x;
    if (idx >= GG * NC) return;
    int g = idx / NC, c = idx % NC;
    float acc = 0.f;
#pragma unroll
    for (int l = 0; l < NL + 1; l++) {
        acc += jkb[l * NC + c];
        const float* p = g_pooled + ((size_t)l * GG + g) * CH;
        const float* w = jkW + l * CH * NC + c;
        float a = 0.f;
#pragma unroll 8
        for (int k = 0; k < CH; k++) a += p[k] * w[k * NC];
        acc += a;
    }
    out[idx] = acc;
}

// ------------------------- host launch -------------------------------------
extern "C" void kernel_launch(void* const* d_in, const int* in_sizes, int n_in,
                              void* d_out, int out_size) {
    (void)in_sizes; (void)n_in; (void)out_size;
    const float* h_in   = (const float*)d_in[0];
    const float* eattr  = (const float*)d_in[1];
    const int*   ei     = (const int*)d_in[2];
    const int*   batch  = (const int*)d_in[5];
    const float* embW   = (const float*)d_in[6];
    const float* embB   = (const float*)d_in[7];
    const float* convW  = (const float*)d_in[8];
    const float* convB  = (const float*)d_in[9];
    const float* convWe = (const float*)d_in[10];
    const float* convBe = (const float*)d_in[11];
    const float* gamma  = (const float*)d_in[12];
    const float* beta   = (const float*)d_in[13];
    const float* jkW    = (const float*)d_in[14];
    const float* jkb    = (const float*)d_in[15];
    float* out = (float*)d_out;

    void *p_deg, *p_pooled, *p_stats, *p_h, *p_x, *p_z;
    cudaGetSymbolAddress(&p_deg, g_deg);
    cudaGetSymbolAddress(&p_pooled, g_pooled);
    cudaGetSymbolAddress(&p_stats, g_stats);
    cudaGetSymbolAddress(&p_h, g_h);
    cudaGetSymbolAddress(&p_x, g_x);
    cudaGetSymbolAddress(&p_z, g_z);

    const int smem_g = (CH * CH + CH + TILE * CH) * (int)sizeof(float);
    cudaFuncSetAttribute(k_gemm<false>, cudaFuncAttributeMaxDynamicSharedMemorySize, smem_g);
    cudaFuncSetAttribute(k_gemm<true>, cudaFuncAttributeMaxDynamicSharedMemorySize, smem_g);

    cudaMemsetAsync(p_deg, 0, NN * sizeof(int));
    cudaMemsetAsync(p_stats, 0, NL * 2 * CH * sizeof(float));
    cudaMemsetAsync(p_pooled, 0, (NL + 1) * GG * CH * sizeof(float));

    const int nb = (NN + 1023) / 1024;  // 49
    k_deg<<<(EE + 255) / 256, 256>>>(ei);                                 // k1
    k_scan1<<<nb, 1024>>>();                                              // k2
    k_scan3<<<nb, 1024>>>(nb);                                            // k3
    k_gemm<false><<<296, 256, smem_g>>>(h_in, embW, embB, (float*)p_h, nullptr); // k4 (profiled)
    k_fill<<<(EE + 255) / 256, 256>>>(ei);
    k_ea<<<(NN * 16 + 255) / 256, 256>>>(eattr);
    k_pool0<<<dim3(GG, 4), CH>>>(batch, (float*)p_pooled);

    for (int l = 0; l < NL; l++) {
        k_aggregate<<<(NN * 32 + 255) / 256, 256>>>(convWe + (size_t)l * EF * CH,
                                                    convBe + (size_t)l * CH);
        k_gemm<true><<<296, 256, smem_g>>>((const float*)p_x,
                                           convW + (size_t)l * CH * CH,
                                           convB + (size_t)l * CH,
                                           (float*)p_z,
                                           (float*)p_stats + (size_t)l * 2 * CH);
        k_poolbn<<<dim3(GG, 4), CH>>>((const float*)p_stats + (size_t)l * 2 * CH,
                                      gamma + (size_t)l * CH, beta + (size_t)l * CH,
                                      batch, (float*)p_pooled + (size_t)(l + 1) * GG * CH);
    }

    k_jk<<<(GG * NC + 255) / 256, 256>>>(jkW, jkb, out);
}

// round 17
// speedup vs baseline: 1.0358x; 1.0358x over previous
#include <cuda_runtime.h>

#define NN 50000
#define EE 800000
#define GG 500
#define CH 128
#define EF 16
#define NL 4
#define NC 10
#define BN_EPS 1e-5f

// packed-f32x2 FMA (Blackwell): d.{lo,hi} += a.{lo,hi} * b.{lo,hi}
#define FMA2(d, a, b) asm("fma.rn.f32x2 %0, %1, %2, %0;" : "+l"(d) : "l"(a), "l"(b))

#define TR 8                // rows per warp (GEMM)
#define NWARP 8             // warps per block (GEMM)
#define TILE (NWARP * TR)   // 64 rows per block
#define WST 132             // transposed-W row stride: conflict-free per
                            // quarter-warp phase (quad = 33*l mod 8 distinct)

// ------------------------- scratch (device globals, no allocation) ---------
__device__ __align__(16) float g_h[NN * CH];
__device__ __align__(16) float g_x[NN * CH];
__device__ __align__(16) float g_z[NN * CH];
__device__ __align__(16) float g_ea[NN * EF];
__device__ int   g_deg[NN];
__device__ int   g_rowptr[NN + 1];
__device__ int   g_cursor[NN];
__device__ int   g_col[EE];   // CSR: src sorted by dst
__device__ int   g_eid[EE];   // CSR: edge id sorted by dst
__device__ int   g_bsum[64];
__device__ __align__(16) float g_stats[NL * 2 * CH];
__device__ __align__(16) float g_pooled[(NL + 1) * GG * CH];

// ------------------------- degree count ------------------------------------
__global__ void k_deg(const int* __restrict__ ei) {
    int e = blockIdx.x * blockDim.x + threadIdx.x;
    if (e >= EE) return;
    atomicAdd(&g_deg[ei[EE + e]], 1);
}

// ------------------------- scan pass 1: per-block sums ---------------------
__global__ void k_scan1() {
    __shared__ int s[1024];
    int i = blockIdx.x * 1024 + threadIdx.x;
    s[threadIdx.x] = (i < NN) ? g_deg[i] : 0;
    __syncthreads();
    for (int off = 512; off > 0; off >>= 1) {
        if (threadIdx.x < off) s[threadIdx.x] += s[threadIdx.x + off];
        __syncthreads();
    }
    if (threadIdx.x == 0) g_bsum[blockIdx.x] = s[0];
}

// ------------- scan pass 2: per-block base + local scan --------------------
__global__ void k_scan3(int nb) {
    __shared__ int s[1024];
    __shared__ int base;
    if (threadIdx.x == 0) {
        int run = 0;
        for (int b = 0; b < blockIdx.x; b++) run += g_bsum[b];
        base = run;
        if (blockIdx.x == 0) g_rowptr[NN] = EE;
    }
    int i = blockIdx.x * 1024 + threadIdx.x;
    int v = (i < NN) ? g_deg[i] : 0;
    s[threadIdx.x] = v;
    __syncthreads();
    for (int off = 1; off < 1024; off <<= 1) {
        int t = (threadIdx.x >= off) ? s[threadIdx.x - off] : 0;
        __syncthreads();
        s[threadIdx.x] += t;
        __syncthreads();
    }
    if (i < NN) {
        int r = s[threadIdx.x] - v + base;
        g_rowptr[i] = r;
        g_cursor[i] = r;
    }
}

// ------------------------- CSR fill ----------------------------------------
__global__ void k_fill(const int* __restrict__ ei) {
    int e = blockIdx.x * blockDim.x + threadIdx.x;
    if (e >= EE) return;
    int d = ei[EE + e];
    int pos = atomicAdd(&g_cursor[d], 1);
    g_col[pos] = ei[e];
    g_eid[pos] = e;
}

// ------------------------- ea = segment_sum(edge_attr, dst) ----------------
__global__ void k_ea(const float* __restrict__ eattr) {
    int idx = blockIdx.x * blockDim.x + threadIdx.x;
    int n = idx >> 4;
    if (n >= NN) return;
    int k = idx & 15;
    int beg = g_rowptr[n], end = g_rowptr[n + 1];
    float a0 = 0.f, a1 = 0.f;
    int e = beg;
    for (; e + 2 <= end; e += 2) {
        int i0 = g_eid[e], i1 = g_eid[e + 1];
        a0 += eattr[(size_t)i0 * EF + k];
        a1 += eattr[(size_t)i1 * EF + k];
    }
    if (e < end) a0 += eattr[(size_t)g_eid[e] * EF + k];
    g_ea[(size_t)n * EF + k] = a0 + a1;
}

// ---------- aggregate (standalone, high occupancy): x = h + deg*be + ea@We
// ---------- + sum h[src] ; warp per node, MLP=8 on the edge loop -----------
__global__ void __launch_bounds__(256)
k_aggregate(const float* __restrict__ We, const float* __restrict__ be) {
    __shared__ float Wes[EF * CH];
    __shared__ float bes[CH];
    for (int i = threadIdx.x; i < EF * CH; i += blockDim.x) Wes[i] = We[i];
    if (threadIdx.x < CH) bes[threadIdx.x] = be[threadIdx.x];
    __syncthreads();

    int n = (blockIdx.x * blockDim.x + threadIdx.x) >> 5;
    if (n >= NN) return;
    int lane = threadIdx.x & 31;
    int c0 = lane * 4;

    float4 acc = *(const float4*)(g_h + (size_t)n * CH + c0);
    float4 ac2 = make_float4(0.f, 0.f, 0.f, 0.f);
    float4 ac3 = make_float4(0.f, 0.f, 0.f, 0.f);
    float4 ac4 = make_float4(0.f, 0.f, 0.f, 0.f);

    int beg = g_rowptr[n], end = g_rowptr[n + 1];
    float dg = (float)(end - beg);
    float4 b4 = *(const float4*)&bes[c0];
    acc.x += dg * b4.x; acc.y += dg * b4.y;
    acc.z += dg * b4.z; acc.w += dg * b4.w;

#pragma unroll
    for (int k = 0; k < EF; k++) {
        float ev = g_ea[(size_t)n * EF + k];
        float4 w = *(const float4*)&Wes[k * CH + c0];
        acc.x += ev * w.x; acc.y += ev * w.y;
        acc.z += ev * w.z; acc.w += ev * w.w;
    }

    int e = beg;
    for (; e + 8 <= end; e += 8) {
        int s0 = g_col[e],     s1 = g_col[e + 1];
        int s2 = g_col[e + 2], s3 = g_col[e + 3];
        int s4 = g_col[e + 4], s5 = g_col[e + 5];
        int s6 = g_col[e + 6], s7 = g_col[e + 7];
        float4 v0 = *(const float4*)(g_h + (size_t)s0 * CH + c0);
        float4 v1 = *(const float4*)(g_h + (size_t)s1 * CH + c0);
        float4 v2 = *(const float4*)(g_h + (size_t)s2 * CH + c0);
        float4 v3 = *(const float4*)(g_h + (size_t)s3 * CH + c0);
        float4 v4 = *(const float4*)(g_h + (size_t)s4 * CH + c0);
        float4 v5 = *(const float4*)(g_h + (size_t)s5 * CH + c0);
        float4 v6 = *(const float4*)(g_h + (size_t)s6 * CH + c0);
        float4 v7 = *(const float4*)(g_h + (size_t)s7 * CH + c0);
        acc.x += v0.x + v1.x; ac2.x += v2.x + v3.x;
        ac3.x += v4.x + v5.x; ac4.x += v6.x + v7.x;
        acc.y += v0.y + v1.y; ac2.y += v2.y + v3.y;
        ac3.y += v4.y + v5.y; ac4.y += v6.y + v7.y;
        acc.z += v0.z + v1.z; ac2.z += v2.z + v3.z;
        ac3.z += v4.z + v5.z; ac4.z += v6.z + v7.z;
        acc.w += v0.w + v1.w; ac2.w += v2.w + v3.w;
        ac3.w += v4.w + v5.w; ac4.w += v6.w + v7.w;
    }
    for (; e + 2 <= end; e += 2) {
        int s0 = g_col[e], s1 = g_col[e + 1];
        float4 v0 = *(const float4*)(g_h + (size_t)s0 * CH + c0);
        float4 v1 = *(const float4*)(g_h + (size_t)s1 * CH + c0);
        ac2.x += v0.x + v1.x; ac2.y += v0.y + v1.y;
        ac2.z += v0.z + v1.z; ac2.w += v0.w + v1.w;
    }
    if (e < end) {
        int s = g_col[e];
        float4 v = *(const float4*)(g_h + (size_t)s * CH + c0);
        ac3.x += v.x; ac3.y += v.y; ac3.z += v.z; ac3.w += v.w;
    }
    acc.x += (ac2.x + ac3.x) + ac4.x;
    acc.y += (ac2.y + ac3.y) + ac4.y;
    acc.z += (ac2.z + ac3.z) + ac4.z;
    acc.w += (ac2.w + ac3.w) + ac4.w;

    *(float4*)(g_x + (size_t)n * CH + c0) = acc;
}

// ===== GEMM core: k-pair packing, transposed W (stride 132), pack-free =====
// Lane owns cols {lane, lane+32, lane+64, lane+96}. acc[r][j] is f32x2 over
// (even-k, odd-k) partial sums. Per chunk of 4 k: 4 W LDS.128 (fixed base
// pointers, immediate offsets) + 8 x LDS.128 (warp-broadcast) + 64 FMA2.
template <bool STATS>
__device__ __forceinline__ void gemm_tile_kp(
    const float* __restrict__ Wt, const float* __restrict__ xs,
    const float* __restrict__ bs,
    int tile, int r0, int lane, float* __restrict__ Z,
    float* cs, float* cq) {

    unsigned long long acc[TR][4];
#pragma unroll
    for (int r = 0; r < TR; r++)
#pragma unroll
        for (int j = 0; j < 4; j++) acc[r][j] = 0ull;

    const float* w0p = &Wt[(lane +  0) * WST];
    const float* w1p = &Wt[(lane + 32) * WST];
    const float* w2p = &Wt[(lane + 64) * WST];
    const float* w3p = &Wt[(lane + 96) * WST];

#pragma unroll 4
    for (int k = 0; k < CH; k += 4) {
        ulonglong2 w0 = *(const ulonglong2*)&w0p[k];
        ulonglong2 w1 = *(const ulonglong2*)&w1p[k];
        ulonglong2 w2 = *(const ulonglong2*)&w2p[k];
        ulonglong2 w3 = *(const ulonglong2*)&w3p[k];
#pragma unroll
        for (int r = 0; r < TR; r++) {
            ulonglong2 xp = *(const ulonglong2*)&xs[(r0 + r) * CH + k]; // broadcast
            FMA2(acc[r][0], xp.x, w0.x);
            FMA2(acc[r][1], xp.x, w1.x);
            FMA2(acc[r][2], xp.x, w2.x);
            FMA2(acc[r][3], xp.x, w3.x);
            FMA2(acc[r][0], xp.y, w0.y);
            FMA2(acc[r][1], xp.y, w1.y);
            FMA2(acc[r][2], xp.y, w2.y);
            FMA2(acc[r][3], xp.y, w3.y);
        }
    }

#pragma unroll
    for (int r = 0; r < TR; r++) {
        int m = tile + r0 + r;
        if (m < NN) {
#pragma unroll
            for (int j = 0; j < 4; j++) {
                int c = lane + 32 * j;
                float lo = __uint_as_float((unsigned)acc[r][j]);
                float hi = __uint_as_float((unsigned)(acc[r][j] >> 32));
                float v = lo + hi + bs[c];
                Z[(size_t)m * CH + c] = v;   // coalesced: lanes -> consecutive c
                if (STATS) { cs[j] += v; cq[j] += v * v; }
            }
        }
    }
}

// ------------------------- GEMM: Z = X@W + b (+ optional BN stats) ----------
template <bool STATS>
__global__ void __launch_bounds__(256, 2)
k_gemm(const float* __restrict__ X, const float* __restrict__ W,
       const float* __restrict__ B, float* __restrict__ Z,
       float* __restrict__ stats) {
    extern __shared__ float sm[];
    float* Wt = sm;                  // 128*132 (transposed, skewed stride)
    float* bs = Wt + CH * WST;       // 128
    float* xs = bs + CH;             // TILE*128

    for (int i = threadIdx.x; i < CH * CH; i += 256) {
        int k = i >> 7, c = i & 127;
        Wt[c * WST + k] = W[i];
    }
    if (threadIdx.x < CH) bs[threadIdx.x] = B[threadIdx.x];
    __syncthreads();

    int warp = threadIdx.x >> 5, lane = threadIdx.x & 31;
    int c0 = lane * 4, r0 = warp * TR;
    float cs[4] = {0.f, 0.f, 0.f, 0.f};
    float cq[4] = {0.f, 0.f, 0.f, 0.f};

    for (int tile = blockIdx.x * TILE; tile < NN; tile += gridDim.x * TILE) {
#pragma unroll
        for (int r = 0; r < TR; r++) {
            int m = tile + r0 + r;
            float4 v = make_float4(0.f, 0.f, 0.f, 0.f);
            if (m < NN) v = *(const float4*)(X + (size_t)m * CH + c0);
            *(float4*)&xs[(r0 + r) * CH + c0] = v;
        }
        __syncwarp();   // warp-private slice: intra-warp ordering only
        gemm_tile_kp<STATS>(Wt, xs, bs, tile, r0, lane, Z, cs, cq);
        __syncwarp();   // WAR before next overwrite
    }

    if (STATS) {
        __syncthreads();
        float* sr = xs;
        sr[threadIdx.x] = 0.f;
        __syncthreads();
#pragma unroll
        for (int j = 0; j < 4; j++) {
            int c = lane + 32 * j;
            atomicAdd(&sr[c], cs[j]);
            atomicAdd(&sr[CH + c], cq[j]);
        }
        __syncthreads();
        atomicAdd(&stats[threadIdx.x], sr[threadIdx.x]);
    }
}

// --- BN(from stats) + relu + residual + partial pool: grid (GG, 4) ---------
__global__ void k_poolbn(const float* __restrict__ stats,
                         const float* __restrict__ gamma,
                         const float* __restrict__ beta,
                         const int* __restrict__ batch,
                         float* __restrict__ pooled) {
    __shared__ int s_lo, s_hi;
    int g = blockIdx.x, part = blockIdx.y, c = threadIdx.x;

    float mu = stats[c] * (1.0f / NN);
    float var = stats[CH + c] * (1.0f / NN) - mu * mu;
    float sc = gamma[c] * rsqrtf(var + BN_EPS);
    float sh = beta[c] - mu * sc;

    if (c < 2) {
        int tgt = g + c;
        int lo = 0, hi = NN;
        while (lo < hi) {
            int mid = (lo + hi) >> 1;
            if (batch[mid] < tgt) lo = mid + 1; else hi = mid;
        }
        if (c == 0) s_lo = lo; else s_hi = lo;
    }
    __syncthreads();
    int gs = s_lo, ge = s_hi;
    int len = ge - gs;
    int per = (len + 3) >> 2;
    int lo = gs + part * per;
    int hi = lo + per; if (hi > ge) hi = ge;
    if (lo >= hi) { return; }

    float a0 = 0.f, a1 = 0.f;
    int n = lo;
    for (; n + 2 <= hi; n += 2) {
        float z0 = g_z[(size_t)n * CH + c];
        float h0 = g_h[(size_t)n * CH + c];
        float z1 = g_z[(size_t)(n + 1) * CH + c];
        float h1 = g_h[(size_t)(n + 1) * CH + c];
        float o0 = fmaxf(fmaf(z0, sc, sh), 0.f) + h0;
        float o1 = fmaxf(fmaf(z1, sc, sh), 0.f) + h1;
        g_h[(size_t)n * CH + c] = o0;
        g_h[(size_t)(n + 1) * CH + c] = o1;
        a0 += o0; a1 += o1;
    }
    if (n < hi) {
        float z0 = g_z[(size_t)n * CH + c];
        float h0 = g_h[(size_t)n * CH + c];
        float o0 = fmaxf(fmaf(z0, sc, sh), 0.f) + h0;
        g_h[(size_t)n * CH + c] = o0;
        a0 += o0;
    }
    atomicAdd(&pooled[(size_t)g * CH + c], a0 + a1);
}

// ------------------------- pool layer 0: grid (GG, 4) ----------------------
__global__ void k_pool0(const int* __restrict__ batch, float* __restrict__ pooled) {
    __shared__ int s_lo, s_hi;
    int g = blockIdx.x, part = blockIdx.y, c = threadIdx.x;
    if (c < 2) {
        int tgt = g + c;
        int lo = 0, hi = NN;
        while (lo < hi) {
            int mid = (lo + hi) >> 1;
            if (batch[mid] < tgt) lo = mid + 1; else hi = mid;
        }
        if (c == 0) s_lo = lo; else s_hi = lo;
    }
    __syncthreads();
    int gs = s_lo, ge = s_hi;
    int len = ge - gs;
    int per = (len + 3) >> 2;
    int lo = gs + part * per;
    int hi = lo + per; if (hi > ge) hi = ge;
    if (lo >= hi) return;

    float a0 = 0.f, a1 = 0.f;
    int n = lo;
    for (; n + 2 <= hi; n += 2) {
        a0 += g_h[(size_t)n * CH + c];
        a1 += g_h[(size_t)(n + 1) * CH + c];
    }
    if (n < hi) a0 += g_h[(size_t)n * CH + c];
    atomicAdd(&pooled[(size_t)g * CH + c], a0 + a1);
}

// ------------------------- JK heads ----------------------------------------
__global__ void k_jk(const float* __restrict__ jkW, const float* __restrict__ jkb,
                     float* __restrict__ out) {
    int idx = blockIdx.x * blockDim.x + threadIdx.x;
    if (idx >= GG * NC) return;
    int g = idx / NC, c = idx % NC;
    float acc = 0.f;
#pragma unroll
    for (int l = 0; l < NL + 1; l++) {
        acc += jkb[l * NC + c];
        const float* p = g_pooled + ((size_t)l * GG + g) * CH;
        const float* w = jkW + l * CH * NC + c;
        float a = 0.f;
#pragma unroll 8
        for (int k = 0; k < CH; k++) a += p[k] * w[k * NC];
        acc += a;
    }
    out[idx] = acc;
}

// ------------------------- host launch -------------------------------------
extern "C" void kernel_launch(void* const* d_in, const int* in_sizes, int n_in,
                              void* d_out, int out_size) {
    (void)in_sizes; (void)n_in; (void)out_size;
    const float* h_in   = (const float*)d_in[0];
    const float* eattr  = (const float*)d_in[1];
    const int*   ei     = (const int*)d_in[2];
    const int*   batch  = (const int*)d_in[5];
    const float* embW   = (const float*)d_in[6];
    const float* embB   = (const float*)d_in[7];
    const float* convW  = (const float*)d_in[8];
    const float* convB  = (const float*)d_in[9];
    const float* convWe = (const float*)d_in[10];
    const float* convBe = (const float*)d_in[11];
    const float* gamma  = (const float*)d_in[12];
    const float* beta   = (const float*)d_in[13];
    const float* jkW    = (const float*)d_in[14];
    const float* jkb    = (const float*)d_in[15];
    float* out = (float*)d_out;

    void *p_deg, *p_pooled, *p_stats, *p_h, *p_x, *p_z;
    cudaGetSymbolAddress(&p_deg, g_deg);
    cudaGetSymbolAddress(&p_pooled, g_pooled);
    cudaGetSymbolAddress(&p_stats, g_stats);
    cudaGetSymbolAddress(&p_h, g_h);
    cudaGetSymbolAddress(&p_x, g_x);
    cudaGetSymbolAddress(&p_z, g_z);

    const int smem_g = (CH * WST + CH + TILE * CH) * (int)sizeof(float);
    cudaFuncSetAttribute(k_gemm<false>, cudaFuncAttributeMaxDynamicSharedMemorySize, smem_g);
    cudaFuncSetAttribute(k_gemm<true>, cudaFuncAttributeMaxDynamicSharedMemorySize, smem_g);

    cudaMemsetAsync(p_deg, 0, NN * sizeof(int));
    cudaMemsetAsync(p_stats, 0, NL * 2 * CH * sizeof(float));
    cudaMemsetAsync(p_pooled, 0, (NL + 1) * GG * CH * sizeof(float));

    const int nb = (NN + 1023) / 1024;  // 49
    k_deg<<<(EE + 255) / 256, 256>>>(ei);                                 // k1
    k_scan1<<<nb, 1024>>>();                                              // k2
    k_scan3<<<nb, 1024>>>(nb);                                            // k3
    k_gemm<false><<<296, 256, smem_g>>>(h_in, embW, embB, (float*)p_h, nullptr); // k4 (profiled)
    k_fill<<<(EE + 255) / 256, 256>>>(ei);
    k_ea<<<(NN * 16 + 255) / 256, 256>>>(eattr);
    k_pool0<<<dim3(GG, 4), CH>>>(batch, (float*)p_pooled);

    for (int l = 0; l < NL; l++) {
        k_aggregate<<<(NN * 32 + 255) / 256, 256>>>(convWe + (size_t)l * EF * CH,
                                                    convBe + (size_t)l * CH);
        k_gemm<true><<<296, 256, smem_g>>>((const float*)p_x,
                                           convW + (size_t)l * CH * CH,
                                           convB + (size_t)l * CH,
                                           (float*)p_z,
                                           (float*)p_stats + (size_t)l * 2 * CH);
        k_poolbn<<<dim3(GG, 4), CH>>>((const float*)p_stats + (size_t)l * 2 * CH,
                                      gamma + (size_t)l * CH, beta + (size_t)l * CH,
                                      batch, (float*)p_pooled + (size_t)(l + 1) * GG * CH);
    }

    k_jk<<<(GG * NC + 255) / 256, 256>>>(jkW, jkb, out);
}